// round 12
// baseline (speedup 1.0000x reference)
#include <cuda_runtime.h>
#include <cuda_bf16.h>

// B=16, C=3, H=256, w=5 -> 246x246 interior centers x 120 shifts.
// F = sum_{a in image} sum_{d in D+} ([a in I] + [a+d in I]) * pairT(a,a+d)
// (= 2M + P - N; boundary folded into weights, no correction blocks).
// R12: abs via FADD operand modifiers (free) instead of u64 LOP3 masks:
// per-eval issue slots 13 (7 fma + 6 alu) -> 9 (all fma). Bit-identical output.
#define HH    256
#define WW    5
#define TX    32
#define TYT   32
#define KP    4
#define NT    256            // 32 x 8 threads
#define HX    (TX + 2*WW)    // 42
#define HROWS 37
#define NB    16
#define NMAIN (8*8*NB)       // 1024

typedef unsigned long long u64;

__device__ float g_partials[NMAIN];
__device__ int   g_done = 0;

__device__ __forceinline__ u64 f2_add(u64 a, u64 b) {
    u64 r;
    asm("add.rn.f32x2 %0, %1, %2;" : "=l"(r) : "l"(a), "l"(b));
    return r;
}

__device__ __forceinline__ float f2_lo(u64 v) {
    return __uint_as_float((unsigned)v);
}
__device__ __forceinline__ float f2_hi(u64 v) {
    return __uint_as_float((unsigned)(v >> 32));
}

// Interior test: image coord v in [5, 250]  <=>  (unsigned)(v-5) <= 245.
__device__ __forceinline__ bool in_I(int v) {
    return (unsigned)(v - WW) <= 245u;
}

template <bool EDGE>
__device__ __forceinline__ float compute_tile(const u64 (*sh)[HROWS * HX],
                                              int px, int ry0,
                                              int X0, int Y0) {
    const u64 SGN = 0x8000000080000000ULL;

    u64 nc0[KP], nc1[KP], nc2[KP];
    float wa[KP];
    #pragma unroll
    for (int p = 0; p < KP; ++p) {
        int ci = (ry0 + p) * HX + (px + WW);
        nc0[p] = sh[0][ci] ^ SGN;
        nc1[p] = sh[1][ci] ^ SGN;
        nc2[p] = sh[2][ci] ^ SGN;
        if (EDGE)
            wa[p] = (in_I(X0 + px) && in_I(Y0 + ry0 + p)) ? 1.f : 0.f;
    }
    float acc[KP];
    #pragma unroll
    for (int p = 0; p < KP; ++p) acc[p] = 0.f;

    // ---- loop A: dx in [-5,0], dy in [1,5] ----
    for (int dx = -5; dx <= 0; ++dx) {
        const int base = ry0 * HX + (px + WW + dx);
        float bx = 0.f;
        if (EDGE) bx = in_I(X0 + px + dx) ? 1.f : 0.f;
        #pragma unroll
        for (int rr = 1; rr <= KP + 4; ++rr) {
            float wb = 0.f;
            if (EDGE) wb = in_I(Y0 + ry0 + rr) ? bx : 0.f;  // partner y indep of p
            const u64 v0 = sh[0][base + rr * HX];
            const u64 v1 = sh[1][base + rr * HX];
            const u64 v2 = sh[2][base + rr * HX];
            #pragma unroll
            for (int p = 0; p < KP; ++p) {
                const int dy = rr - p;
                if (dy >= 1 && dy <= 5) {
                    u64 d0 = f2_add(nc0[p], v0);   // (v - c) packed (orig,sim)
                    u64 d1 = f2_add(nc1[p], v1);
                    u64 d2 = f2_add(nc2[p], v2);
                    // fabsf folds into FADD operand modifiers (no LOP3)
                    float sO = fabsf(f2_lo(d0)) + fabsf(f2_lo(d1));
                    sO += fabsf(f2_lo(d2));
                    float sS = fabsf(f2_hi(d0)) + fabsf(f2_hi(d1));
                    sS += fabsf(f2_hi(d2));
                    float d = sO - sS;
                    if (EDGE) acc[p] = fmaf(wa[p] + wb, fabsf(d), acc[p]);
                    else      acc[p] += fabsf(d);
                }
            }
        }
    }
    // ---- loop B: dx in [1,5], dy in [0,5] ----
    for (int dx = 1; dx <= 5; ++dx) {
        const int base = ry0 * HX + (px + WW + dx);
        float bx = 0.f;
        if (EDGE) bx = in_I(X0 + px + dx) ? 1.f : 0.f;
        #pragma unroll
        for (int rr = 0; rr <= KP + 4; ++rr) {
            float wb = 0.f;
            if (EDGE) wb = in_I(Y0 + ry0 + rr) ? bx : 0.f;
            const u64 v0 = sh[0][base + rr * HX];
            const u64 v1 = sh[1][base + rr * HX];
            const u64 v2 = sh[2][base + rr * HX];
            #pragma unroll
            for (int p = 0; p < KP; ++p) {
                const int dy = rr - p;
                if (dy >= 0 && dy <= 5) {
                    u64 d0 = f2_add(nc0[p], v0);
                    u64 d1 = f2_add(nc1[p], v1);
                    u64 d2 = f2_add(nc2[p], v2);
                    float sO = fabsf(f2_lo(d0)) + fabsf(f2_lo(d1));
                    sO += fabsf(f2_lo(d2));
                    float sS = fabsf(f2_hi(d0)) + fabsf(f2_hi(d1));
                    sS += fabsf(f2_hi(d2));
                    float d = sO - sS;
                    if (EDGE) acc[p] = fmaf(wa[p] + wb, fabsf(d), acc[p]);
                    else      acc[p] += fabsf(d);
                }
            }
        }
    }

    float t = 0.f;
    #pragma unroll
    for (int p = 0; p < KP; ++p) t += acc[p];
    if (!EDGE) t *= 2.f;     // weight==2 for every pair in a pure tile
    return t;
}

__global__ __launch_bounds__(NT, 3)
void contrast_loss_kernel(const float* __restrict__ gO,
                          const float* __restrict__ gS,
                          float* __restrict__ out) {
    __shared__ u64   sh[3][HROWS * HX];
    __shared__ float red[NT / 32];
    __shared__ int   last_flag;

    const int tid = threadIdx.x;
    const int bid = blockIdx.x;
    const int px  = tid & 31;
    const int ty  = tid >> 5;          // 0..7

    const int b   = bid >> 6;
    const int tyi = (bid >> 3) & 7;
    const int txi = bid & 7;
    const int Y0  = tyi * TYT;         // tile origin, image coords
    const int X0  = txi * TX;

    // ---- halo load: rows Y0..Y0+36, cols X0-5..X0+36; zero-fill off-image ----
    const float* oB = gO + (size_t)b * 3 * HH * HH;
    const float* sB = gS + (size_t)b * 3 * HH * HH;
    for (int idx = tid; idx < 3 * HROWS * HX; idx += NT) {
        int c   = idx / (HROWS * HX);
        int rm  = idx - c * (HROWS * HX);
        int r   = rm / HX;
        int col = rm - r * HX;
        int iy = Y0 + r;
        int ix = X0 - WW + col;
        float vo = 0.f, vs = 0.f;
        if (iy < HH && (unsigned)ix < (unsigned)HH) {
            int off = (c * HH + iy) * HH + ix;
            vo = oB[off];
            vs = sB[off];
        }
        sh[c][rm] = (u64)__float_as_uint(vo)
                  | ((u64)__float_as_uint(vs) << 32);
    }
    __syncthreads();

    const int ry0 = ty * KP;           // 0,4,...,28
    const bool pure = (txi >= 1 && txi <= 6 && tyi >= 1 && tyi <= 6);

    float total = pure ? compute_tile<false>(sh, px, ry0, X0, Y0)
                       : compute_tile<true >(sh, px, ry0, X0, Y0);

    // ---- deterministic block reduction ----
    #pragma unroll
    for (int o = 16; o > 0; o >>= 1)
        total += __shfl_xor_sync(0xffffffffu, total, o);
    if (px == 0) red[ty] = total;
    __syncthreads();
    if (tid == 0) {
        float s = 0.f;
        #pragma unroll
        for (int i = 0; i < NT / 32; ++i) s += red[i];
        g_partials[bid] = s;
    }

    // ---- last block finalizes (fixed order -> deterministic) ----
    if (tid == 0) {
        __threadfence();
        int v = atomicAdd(&g_done, 1);
        last_flag = (v == NMAIN - 1);
    }
    __syncthreads();

    if (last_flag) {
        __threadfence();
        float s = 0.f;
        for (int k = tid; k < NMAIN; k += NT) s += __ldcg(&g_partials[k]);
        #pragma unroll
        for (int o = 16; o > 0; o >>= 1)
            s += __shfl_xor_sync(0xffffffffu, s, o);
        if (px == 0) red[ty] = s;
        __syncthreads();
        if (tid == 0) {
            float t = 0.f;
            #pragma unroll
            for (int i = 0; i < NT / 32; ++i) t += red[i];
            // mean over 16 * 246 * 246 * 120 = 116,190,720 entries
            out[0] = t * (1.0f / 116190720.0f);
            g_done = 0;   // reset for graph replay
        }
    }
}

extern "C" void kernel_launch(void* const* d_in, const int* in_sizes, int n_in,
                              void* d_out, int out_size) {
    const float* orig = (const float*)d_in[0];
    const float* sim  = (const float*)d_in[1];
    float* out = (float*)d_out;

    contrast_loss_kernel<<<NMAIN, NT>>>(orig, sim, out);
}

// round 13
// speedup vs baseline: 1.3960x; 1.3960x over previous
#include <cuda_runtime.h>
#include <cuda_bf16.h>

// B=16, C=3, H=256, w=5 -> 246x246 interior centers x 120 shifts.
// F = sum_{a in image} sum_{d in D+} ([a in I] + [a+d in I]) * pairT(a,a+d)
// (= 2M + P - N; boundary folded into weights, no correction blocks).
// R13: R11 math (proven 54.0us) x R5 warp structure (KP=8, 128 thr — the only
// config that sustained ~70% issue). Packed-mask abs kept (7 fma / 6 alu slots
// per eval dual-issue across pipes; R12 proved 9/0 is worse).
#define HH    256
#define WW    5
#define TX    32
#define TYT   32
#define KP    8
#define NT    128            // 32 x 4 threads
#define HX    (TX + 2*WW)    // 42
#define HROWS 37
#define NB    16
#define NMAIN (8*8*NB)       // 1024

typedef unsigned long long u64;

__device__ float g_partials[NMAIN];
__device__ int   g_done = 0;

__device__ __forceinline__ u64 f2_add(u64 a, u64 b) {
    u64 r;
    asm("add.rn.f32x2 %0, %1, %2;" : "=l"(r) : "l"(a), "l"(b));
    return r;
}

// Interior test: image coord v in [5, 250]  <=>  (unsigned)(v-5) <= 245.
__device__ __forceinline__ bool in_I(int v) {
    return (unsigned)(v - WW) <= 245u;
}

template <bool EDGE>
__device__ __forceinline__ float compute_tile(const u64 (*sh)[HROWS * HX],
                                              int px, int ry0,
                                              int X0, int Y0) {
    const u64 SGN  = 0x8000000080000000ULL;
    const u64 ABSM = 0x7fffffff7fffffffULL;

    u64 nc0[KP], nc1[KP], nc2[KP];
    float wa[KP];
    #pragma unroll
    for (int p = 0; p < KP; ++p) {
        int ci = (ry0 + p) * HX + (px + WW);
        nc0[p] = sh[0][ci] ^ SGN;
        nc1[p] = sh[1][ci] ^ SGN;
        nc2[p] = sh[2][ci] ^ SGN;
        if (EDGE)
            wa[p] = (in_I(X0 + px) && in_I(Y0 + ry0 + p)) ? 1.f : 0.f;
    }
    float acc[KP];
    #pragma unroll
    for (int p = 0; p < KP; ++p) acc[p] = 0.f;

    // ---- loop A: dx in [-5,0], dy in [1,5] ----
    for (int dx = -5; dx <= 0; ++dx) {
        const int base = ry0 * HX + (px + WW + dx);
        float bx = 0.f;
        if (EDGE) bx = in_I(X0 + px + dx) ? 1.f : 0.f;
        #pragma unroll
        for (int rr = 1; rr <= KP + 4; ++rr) {
            float wb = 0.f;
            if (EDGE) wb = in_I(Y0 + ry0 + rr) ? bx : 0.f;  // partner y indep of p
            const u64 v0 = sh[0][base + rr * HX];
            const u64 v1 = sh[1][base + rr * HX];
            const u64 v2 = sh[2][base + rr * HX];
            #pragma unroll
            for (int p = 0; p < KP; ++p) {
                const int dy = rr - p;
                if (dy >= 1 && dy <= 5) {
                    u64 t0 = f2_add(nc0[p], v0) & ABSM;
                    u64 t1 = f2_add(nc1[p], v1) & ABSM;
                    u64 t2 = f2_add(nc2[p], v2) & ABSM;
                    u64 sm = f2_add(f2_add(t0, t1), t2);
                    float d = __uint_as_float((unsigned)sm)
                            - __uint_as_float((unsigned)(sm >> 32));
                    if (EDGE) acc[p] = fmaf(wa[p] + wb, fabsf(d), acc[p]);
                    else      acc[p] += fabsf(d);
                }
            }
        }
    }
    // ---- loop B: dx in [1,5], dy in [0,5] ----
    for (int dx = 1; dx <= 5; ++dx) {
        const int base = ry0 * HX + (px + WW + dx);
        float bx = 0.f;
        if (EDGE) bx = in_I(X0 + px + dx) ? 1.f : 0.f;
        #pragma unroll
        for (int rr = 0; rr <= KP + 4; ++rr) {
            float wb = 0.f;
            if (EDGE) wb = in_I(Y0 + ry0 + rr) ? bx : 0.f;
            const u64 v0 = sh[0][base + rr * HX];
            const u64 v1 = sh[1][base + rr * HX];
            const u64 v2 = sh[2][base + rr * HX];
            #pragma unroll
            for (int p = 0; p < KP; ++p) {
                const int dy = rr - p;
                if (dy >= 0 && dy <= 5) {
                    u64 t0 = f2_add(nc0[p], v0) & ABSM;
                    u64 t1 = f2_add(nc1[p], v1) & ABSM;
                    u64 t2 = f2_add(nc2[p], v2) & ABSM;
                    u64 sm = f2_add(f2_add(t0, t1), t2);
                    float d = __uint_as_float((unsigned)sm)
                            - __uint_as_float((unsigned)(sm >> 32));
                    if (EDGE) acc[p] = fmaf(wa[p] + wb, fabsf(d), acc[p]);
                    else      acc[p] += fabsf(d);
                }
            }
        }
    }

    float t = 0.f;
    #pragma unroll
    for (int p = 0; p < KP; ++p) t += acc[p];
    if (!EDGE) t *= 2.f;     // weight==2 for every pair in a pure tile
    return t;
}

__global__ __launch_bounds__(NT, 4)
void contrast_loss_kernel(const float* __restrict__ gO,
                          const float* __restrict__ gS,
                          float* __restrict__ out) {
    __shared__ u64   sh[3][HROWS * HX];
    __shared__ float red[NT / 32];
    __shared__ int   last_flag;

    const int tid = threadIdx.x;
    const int bid = blockIdx.x;
    const int px  = tid & 31;
    const int ty  = tid >> 5;          // 0..3

    const int b   = bid >> 6;
    const int tyi = (bid >> 3) & 7;
    const int txi = bid & 7;
    const int Y0  = tyi * TYT;         // tile origin, image coords
    const int X0  = txi * TX;

    // ---- halo load: rows Y0..Y0+36, cols X0-5..X0+36; zero-fill off-image ----
    const float* oB = gO + (size_t)b * 3 * HH * HH;
    const float* sB = gS + (size_t)b * 3 * HH * HH;
    for (int idx = tid; idx < 3 * HROWS * HX; idx += NT) {
        int c   = idx / (HROWS * HX);
        int rm  = idx - c * (HROWS * HX);
        int r   = rm / HX;
        int col = rm - r * HX;
        int iy = Y0 + r;
        int ix = X0 - WW + col;
        float vo = 0.f, vs = 0.f;
        if (iy < HH && (unsigned)ix < (unsigned)HH) {
            int off = (c * HH + iy) * HH + ix;
            vo = oB[off];
            vs = sB[off];
        }
        sh[c][rm] = (u64)__float_as_uint(vo)
                  | ((u64)__float_as_uint(vs) << 32);
    }
    __syncthreads();

    const int ry0 = ty * KP;           // 0,8,16,24
    const bool pure = (txi >= 1 && txi <= 6 && tyi >= 1 && tyi <= 6);

    float total = pure ? compute_tile<false>(sh, px, ry0, X0, Y0)
                       : compute_tile<true >(sh, px, ry0, X0, Y0);

    // ---- deterministic block reduction ----
    #pragma unroll
    for (int o = 16; o > 0; o >>= 1)
        total += __shfl_xor_sync(0xffffffffu, total, o);
    if (px == 0) red[ty] = total;
    __syncthreads();
    if (tid == 0) {
        float s = 0.f;
        #pragma unroll
        for (int i = 0; i < NT / 32; ++i) s += red[i];
        g_partials[bid] = s;
    }

    // ---- last block finalizes (fixed order -> deterministic) ----
    if (tid == 0) {
        __threadfence();
        int v = atomicAdd(&g_done, 1);
        last_flag = (v == NMAIN - 1);
    }
    __syncthreads();

    if (last_flag) {
        __threadfence();
        float s = 0.f;
        for (int k = tid; k < NMAIN; k += NT) s += __ldcg(&g_partials[k]);
        #pragma unroll
        for (int o = 16; o > 0; o >>= 1)
            s += __shfl_xor_sync(0xffffffffu, s, o);
        if (px == 0) red[ty] = s;
        __syncthreads();
        if (tid == 0) {
            float t = 0.f;
            #pragma unroll
            for (int i = 0; i < NT / 32; ++i) t += red[i];
            // mean over 16 * 246 * 246 * 120 = 116,190,720 entries
            out[0] = t * (1.0f / 116190720.0f);
            g_done = 0;   // reset for graph replay
        }
    }
}

extern "C" void kernel_launch(void* const* d_in, const int* in_sizes, int n_in,
                              void* d_out, int out_size) {
    const float* orig = (const float*)d_in[0];
    const float* sim  = (const float*)d_in[1];
    float* out = (float*)d_out;

    contrast_loss_kernel<<<NMAIN, NT>>>(orig, sim, out);
}